// round 6
// baseline (speedup 1.0000x reference)
#include <cuda_runtime.h>

// YOLOv1 loss, fused single pass, occupancy-optimized (v2).
// pred/target: [4096, 7, 7, 90] float32 contiguous. Output: scalar float32.
//
// 896 blocks x 8 warps x 28 cells = 200704 cells; 7 blocks/SM resident
// (launch_bounds(256,7)). float2 loads (cell base 360*c bytes is 8B-aligned).
// Lane l holds elements {2l, 2l+1}; lanes<13 also {64+2l, 65+2l}.
//   - class loss: lane>=5 (elems 10..63) + lanes<13 second pair (64..89)
//   - no-obj conf: elem 4 = lane2.x, elem 9 = lane4.y
//   - box floats: lanes 0..4 stage 10+10 floats to smem
// Phase 2: lane i (<28) does full box/IoU/select math for cell i.
// Finalize: warp reduce -> block reduce -> atomicAdd (proven R3 mechanism;
// no device globals, no inter-block tickets).

#define NFEAT 90
#define NCELLS (4096 * 7 * 7)          // 200704
#define INV_BATCH (1.0f / 4096.0f)
#define WARPS_PER_BLOCK 8
#define CELLS_PER_WARP 28
#define NBLOCKS 896                     // 896*8*28 = 200704

__global__ void yolo_zero_kernel(float* out) {
    if (threadIdx.x == 0) out[0] = 0.0f;
}

__global__ __launch_bounds__(256, 7) void yolo_loss_kernel(
    const float* __restrict__ pred,
    const float* __restrict__ target,
    float* __restrict__ out)
{
    const float inv_s = 1.0f / 7.0f;
    const unsigned FULL = 0xffffffffu;

    const int lane   = threadIdx.x & 31;
    const int wid    = threadIdx.x >> 5;
    const int warp_g = blockIdx.x * WARPS_PER_BLOCK + wid;

    // [warp][cell][20 floats + 2 pad]: stride 22 keeps float2 stores 8B-aligned.
    __shared__ float sbuf[WARPS_PER_BLOCK][CELLS_PER_WARP][22];

    float acc = 0.0f;

    const int cell0 = warp_g * CELLS_PER_WARP;

    // ---------------- Phase 1: stream 28 cells ----------------
    #pragma unroll 4
    for (int ci = 0; ci < CELLS_PER_WARP; ci++) {
        const float2* p2 = (const float2*)(pred   + (size_t)(cell0 + ci) * NFEAT);
        const float2* t2 = (const float2*)(target + (size_t)(cell0 + ci) * NFEAT);

        float2 pa = p2[lane];
        float2 ta = t2[lane];
        float2 pb = make_float2(0.0f, 0.0f);
        float2 tb = make_float2(0.0f, 0.0f);
        if (lane < 13) { pb = p2[lane + 32]; tb = t2[lane + 32]; }

        // conf_t = element 4 = lane 2, x component
        float conf_t  = __shfl_sync(FULL, ta.x, 2);
        float coord_m = (conf_t > 0.0f) ? 1.0f : 0.0f;

        float dx = pa.x - ta.x;
        float dy = pa.y - ta.y;

        // class loss: elems 10..63 (lane>=5) and 64..89 (second pair, lane<13)
        if (lane >= 5) acc += coord_m * (dx * dx + dy * dy);
        if (lane < 13) {
            float ex = pb.x - tb.x;
            float ey = pb.y - tb.y;
            acc += coord_m * (ex * ex + ey * ey);
        }

        // no-object confidence loss (elems 4 and 9), weight 0.5
        if (conf_t == 0.0f) {
            if (lane == 2) acc += 0.5f * dx * dx;   // elem 4
            if (lane == 4) acc += 0.5f * dy * dy;   // elem 9
        }

        // stage box/conf floats (elements 0..9 of each tensor)
        if (lane < 5) {
            *(float2*)&sbuf[wid][ci][2 * lane]      = pa;
            *(float2*)&sbuf[wid][ci][2 * lane + 10] = ta;
        }
    }
    __syncwarp();

    // ---------------- Phase 2: box math, one cell per lane ----------------
    if (lane < CELLS_PER_WARP) {
        const float* s = sbuf[wid][lane];
        float pp0 = s[0],  pp1 = s[1],  pp2 = s[2],  pp3 = s[3],  pp4 = s[4];
        float pp5 = s[5],  pp6 = s[6],  pp7 = s[7],  pp8 = s[8],  pp9 = s[9];
        float tt0 = s[10], tt1 = s[11], tt2 = s[12], tt3 = s[13], tt4 = s[14];
        float tt5 = s[15], tt6 = s[16], tt7 = s[17], tt8 = s[18];

        float coord_m = (tt4 > 0.0f) ? 1.0f : 0.0f;

        // pred box 0
        float pax0 = pp0 * inv_s - 0.5f * pp2;
        float pay0 = pp1 * inv_s - 0.5f * pp3;
        float pbx0 = pax0 * inv_s + 0.5f * pp2;
        float pby0 = pay0 * inv_s + 0.5f * pp3;
        // pred box 1
        float pax1 = pp5 * inv_s - 0.5f * pp7;
        float pay1 = pp6 * inv_s - 0.5f * pp8;
        float pbx1 = pax1 * inv_s + 0.5f * pp7;
        float pby1 = pay1 * inv_s + 0.5f * pp8;

        // target box 0
        float tax = tt0 * inv_s - 0.5f * tt2;
        float tay = tt1 * inv_s - 0.5f * tt3;
        float tbx = tax * inv_s + 0.5f * tt2;
        float tby = tay * inv_s + 0.5f * tt3;
        float t_area = (tbx - tax) * (tby - tay);

        // IoU box 0
        float w0 = fmaxf(fminf(pbx0, tbx) - fmaxf(pax0, tax), 0.0f);
        float h0 = fmaxf(fminf(pby0, tby) - fmaxf(pay0, tay), 0.0f);
        float inter0 = w0 * h0;
        float parea0 = (pbx0 - pax0) * (pby0 - pay0);
        float iou0 = inter0 / (parea0 + t_area - inter0);
        // IoU box 1
        float w1 = fmaxf(fminf(pbx1, tbx) - fmaxf(pax1, tax), 0.0f);
        float h1 = fmaxf(fminf(pby1, tby) - fmaxf(pay1, tay), 0.0f);
        float inter1 = w1 * h1;
        float parea1 = (pbx1 - pax1) * (pby1 - pay1);
        float iou1 = inter1 / (parea1 + t_area - inter1);

        bool sel1 = (iou1 > iou0);
        float max_iou = sel1 ? iou1 : iou0;

        float psx = sel1 ? pax1 : pax0;
        float psy = sel1 ? pay1 : pay0;
        float psw = sel1 ? pbx1 : pbx0;
        float psh = sel1 ? pby1 : pby0;
        float psc = sel1 ? pp9  : pp4;

        float tsx = sel1 ? tt5 : tax;
        float tsy = sel1 ? tt6 : tay;
        float tsw = sel1 ? tt7 : tbx;
        float tsh = sel1 ? tt8 : tby;

        float ddx = psx - tsx, ddy = psy - tsy;
        float ddw = psw - tsw, ddh = psh - tsh;
        float xy_wh = ddx * ddx + ddy * ddy + ddw * ddw + ddh * ddh;
        float dc = psc - max_iou;

        acc += coord_m * (5.0f * xy_wh + dc * dc);
    }

    // ---------------- final reduction ----------------
    #pragma unroll
    for (int o = 16; o > 0; o >>= 1)
        acc += __shfl_xor_sync(FULL, acc, o);

    __shared__ float wsum[WARPS_PER_BLOCK];
    if (lane == 0) wsum[wid] = acc;
    __syncthreads();
    if (threadIdx.x == 0) {
        float tot = 0.0f;
        #pragma unroll
        for (int i = 0; i < WARPS_PER_BLOCK; i++) tot += wsum[i];
        atomicAdd(out, tot * INV_BATCH);
    }
}

extern "C" void kernel_launch(void* const* d_in, const int* in_sizes, int n_in,
                              void* d_out, int out_size) {
    const float* pred   = (const float*)d_in[0];
    const float* target = (const float*)d_in[1];
    float* out = (float*)d_out;
    (void)in_sizes; (void)n_in; (void)out_size;

    yolo_zero_kernel<<<1, 32>>>(out);
    yolo_loss_kernel<<<NBLOCKS, 256>>>(pred, target, out);
}

// round 8
// speedup vs baseline: 1.2000x; 1.2000x over previous
#include <cuda_runtime.h>

// YOLOv1 loss, fused single pass, MLP-optimized (float4 cell pairs), v2:
// contiguous per-warp pair mapping.
// pred/target: [4096, 7, 7, 90] float32 contiguous. Output: scalar float32.
//
// Cells processed in PAIRS (180 floats = 45 float4, base 720B = 16B-aligned).
// 1568 blocks x 4 warps x 16 pairs = 100352 pairs = 200704 cells, exact.
// launch_bounds(128,11): 46-reg budget, 11 blocks/SM, single wave.
//
// Per pair, per lane l (all loads unconditional & independent -> high MLP,
// no shfl in the hot loop):
//   pA/tA = float4 #l               (elements 4l..4l+3, covers 0..127)
//   pB/tB = float4 #(min(l,12)+32)  (elements 128..179; lanes>=13 dummy
//           re-read #44, weighted 0)
//   ct0/ct1 = scalar loads of target elems 4 / 94 (HW broadcast)
// Class + no-obj conf accumulated per component via loop-invariant lane
// masks (pure FSEL). Box floats (lanes 0-2 -> cell0, lanes 22-24 -> cell1)
// staged to smem as float4.
// Phase 2: lane k does full box/IoU/select math for staged cell slot k.
// Finalize: warp reduce -> block reduce -> atomicAdd (pre-zeroed out).

#define NFEAT 90
#define INV_BATCH (1.0f / 4096.0f)
#define WARPS_PER_BLOCK 4
#define NBLOCKS 1568             // 1568*4 = 6272 warps
#define PAIRS_PER_WARP 16        // 6272*16 = 100352 pairs = 200704 cells

__global__ void yolo_zero_kernel(float* out) {
    if (threadIdx.x == 0) out[0] = 0.0f;
}

__global__ __launch_bounds__(128, 11) void yolo_loss_kernel(
    const float* __restrict__ pred,
    const float* __restrict__ target,
    float* __restrict__ out)
{
    const float inv_s = 1.0f / 7.0f;
    const unsigned FULL = 0xffffffffu;

    const int lane   = threadIdx.x & 31;
    const int wid    = threadIdx.x >> 5;
    const int warp_g = blockIdx.x * WARPS_PER_BLOCK + wid;

    // [warp][cell slot][24 floats]: pred box floats at [0..11], target at
    // [12..23]. Even slots hold elems 0..11, odd slots hold elems 88..99.
    __shared__ float sbuf[WARPS_PER_BLOCK][32][24];

    // Loop-invariant per-lane component metadata for the first float4:
    // element e = 4*lane + j; cell c = (e>=90); m = e - 90*c.
    bool cJ[4], clsJ[4], cnfJ[4];
    #pragma unroll
    for (int j = 0; j < 4; j++) {
        int e = 4 * lane + j;
        int c = (e >= 90) ? 1 : 0;
        int m = e - 90 * c;
        cJ[j]   = (c != 0);
        clsJ[j] = (m >= 10);
        cnfJ[j] = (m == 4) || (m == 9);
    }
    const int  l2     = (lane < 13 ? lane : 12) + 32;  // second float4 index
    const bool b2live = (lane < 13);                    // second load is real
    const bool stage0 = (lane <= 2);                    // cell0 box floats
    const bool stage1 = (lane >= 22 && lane <= 24);     // cell1 box floats
    const int  soff   = stage0 ? 4 * lane : 4 * lane - 88;

    float acc = 0.0f;

    // ---------------- Phase 1: stream 16 contiguous pairs ----------------
    #pragma unroll 1
    for (int i = 0; i < PAIRS_PER_WARP; i++) {
        const int p = warp_g * PAIRS_PER_WARP + i;
        const float4* P = (const float4*)(pred   + (size_t)p * 180);
        const float4* T = (const float4*)(target + (size_t)p * 180);

        // 6 independent loads, no cross-lane deps
        float4 pA = P[lane];
        float4 tA = T[lane];
        float4 pB = P[l2];
        float4 tB = T[l2];
        float  ct0 = ((const float*)T)[4];    // conf_t of cell 2p
        float  ct1 = ((const float*)T)[94];   // conf_t of cell 2p+1

        float cm0 = (ct0 > 0.0f)  ? 1.0f : 0.0f;
        float cm1 = (ct1 > 0.0f)  ? 1.0f : 0.0f;
        float nb0 = (ct0 == 0.0f) ? 0.5f : 0.0f;
        float nb1 = (ct1 == 0.0f) ? 0.5f : 0.0f;

        // per-component weights (loop-invariant masks -> FSELs)
        float w0 = clsJ[0] ? (cJ[0] ? cm1 : cm0) : (cnfJ[0] ? (cJ[0] ? nb1 : nb0) : 0.0f);
        float w1 = clsJ[1] ? (cJ[1] ? cm1 : cm0) : (cnfJ[1] ? (cJ[1] ? nb1 : nb0) : 0.0f);
        float w2 = clsJ[2] ? (cJ[2] ? cm1 : cm0) : (cnfJ[2] ? (cJ[2] ? nb1 : nb0) : 0.0f);
        float w3 = clsJ[3] ? (cJ[3] ? cm1 : cm0) : (cnfJ[3] ? (cJ[3] ? nb1 : nb0) : 0.0f);
        float wB = b2live ? cm1 : 0.0f;       // elems 128..179: all class, cell1

        float d0 = pA.x - tA.x;
        float d1 = pA.y - tA.y;
        float d2 = pA.z - tA.z;
        float d3 = pA.w - tA.w;
        acc += w0 * d0 * d0 + w1 * d1 * d1 + w2 * d2 * d2 + w3 * d3 * d3;

        float e0 = pB.x - tB.x;
        float e1 = pB.y - tB.y;
        float e2 = pB.z - tB.z;
        float e3 = pB.w - tB.w;
        acc += wB * (e0 * e0 + e1 * e1 + e2 * e2 + e3 * e3);

        // stage box floats
        if (stage0 | stage1) {
            int slot = 2 * i + (stage1 ? 1 : 0);
            *(float4*)&sbuf[wid][slot][soff]      = pA;
            *(float4*)&sbuf[wid][slot][12 + soff] = tA;
        }
    }
    __syncwarp();

    // ---------------- Phase 2: box math, one cell per lane ----------------
    {
        const int  sub  = lane & 1;                 // cell within its pair
        const int  boff = sub ? 2 : 0;              // odd slot: elems start at 88
        const float* s = sbuf[wid][lane];

        float pp0 = s[boff + 0],  pp1 = s[boff + 1],  pp2 = s[boff + 2];
        float pp3 = s[boff + 3],  pp4 = s[boff + 4],  pp5 = s[boff + 5];
        float pp6 = s[boff + 6],  pp7 = s[boff + 7],  pp8 = s[boff + 8];
        float pp9 = s[boff + 9];
        float tt0 = s[12 + boff + 0], tt1 = s[12 + boff + 1], tt2 = s[12 + boff + 2];
        float tt3 = s[12 + boff + 3], tt4 = s[12 + boff + 4], tt5 = s[12 + boff + 5];
        float tt6 = s[12 + boff + 6], tt7 = s[12 + boff + 7], tt8 = s[12 + boff + 8];

        float coord_m = (tt4 > 0.0f) ? 1.0f : 0.0f;

        // pred box 0
        float pax0 = pp0 * inv_s - 0.5f * pp2;
        float pay0 = pp1 * inv_s - 0.5f * pp3;
        float pbx0 = pax0 * inv_s + 0.5f * pp2;
        float pby0 = pay0 * inv_s + 0.5f * pp3;
        // pred box 1
        float pax1 = pp5 * inv_s - 0.5f * pp7;
        float pay1 = pp6 * inv_s - 0.5f * pp8;
        float pbx1 = pax1 * inv_s + 0.5f * pp7;
        float pby1 = pay1 * inv_s + 0.5f * pp8;

        // target box 0
        float tax = tt0 * inv_s - 0.5f * tt2;
        float tay = tt1 * inv_s - 0.5f * tt3;
        float tbx = tax * inv_s + 0.5f * tt2;
        float tby = tay * inv_s + 0.5f * tt3;
        float t_area = (tbx - tax) * (tby - tay);

        // IoU box 0
        float w0 = fmaxf(fminf(pbx0, tbx) - fmaxf(pax0, tax), 0.0f);
        float h0 = fmaxf(fminf(pby0, tby) - fmaxf(pay0, tay), 0.0f);
        float inter0 = w0 * h0;
        float parea0 = (pbx0 - pax0) * (pby0 - pay0);
        float iou0 = inter0 / (parea0 + t_area - inter0);
        // IoU box 1
        float w1 = fmaxf(fminf(pbx1, tbx) - fmaxf(pax1, tax), 0.0f);
        float h1 = fmaxf(fminf(pby1, tby) - fmaxf(pay1, tay), 0.0f);
        float inter1 = w1 * h1;
        float parea1 = (pbx1 - pax1) * (pby1 - pay1);
        float iou1 = inter1 / (parea1 + t_area - inter1);

        bool sel1 = (iou1 > iou0);
        float max_iou = sel1 ? iou1 : iou0;

        float psx = sel1 ? pax1 : pax0;
        float psy = sel1 ? pay1 : pay0;
        float psw = sel1 ? pbx1 : pbx0;
        float psh = sel1 ? pby1 : pby0;
        float psc = sel1 ? pp9  : pp4;

        float tsx = sel1 ? tt5 : tax;
        float tsy = sel1 ? tt6 : tay;
        float tsw = sel1 ? tt7 : tbx;
        float tsh = sel1 ? tt8 : tby;

        float ddx = psx - tsx, ddy = psy - tsy;
        float ddw = psw - tsw, ddh = psh - tsh;
        float xy_wh = ddx * ddx + ddy * ddy + ddw * ddw + ddh * ddh;
        float dc = psc - max_iou;

        acc += coord_m * (5.0f * xy_wh + dc * dc);
    }

    // ---------------- final reduction ----------------
    #pragma unroll
    for (int o = 16; o > 0; o >>= 1)
        acc += __shfl_xor_sync(FULL, acc, o);

    __shared__ float wsum[WARPS_PER_BLOCK];
    if (lane == 0) wsum[wid] = acc;
    __syncthreads();
    if (threadIdx.x == 0) {
        float tot = 0.0f;
        #pragma unroll
        for (int i = 0; i < WARPS_PER_BLOCK; i++) tot += wsum[i];
        atomicAdd(out, tot * INV_BATCH);
    }
}

extern "C" void kernel_launch(void* const* d_in, const int* in_sizes, int n_in,
                              void* d_out, int out_size) {
    const float* pred   = (const float*)d_in[0];
    const float* target = (const float*)d_in[1];
    float* out = (float*)d_out;
    (void)in_sizes; (void)n_in; (void)out_size;

    yolo_zero_kernel<<<1, 32>>>(out);
    yolo_loss_kernel<<<NBLOCKS, 128>>>(pred, target, out);
}